// round 5
// baseline (speedup 1.0000x reference)
#include <cuda_runtime.h>
#include <cstdint>

#define BB  4
#define SS  2048
#define DD  1024
#define HH  16
#define DKK 64
#define NN  (BB*SS)
#define AST 68

// ---- warp-MMA GEMM tiling ----
#define BM   128
#define BN   128
#define BK   8
#define NIT  (DD/BK)            // 128
#define RS   12                 // smem row stride (floats)
#define PLANEF (BM*RS)          // 1536 floats
#define STAGEF (4*PLANEF)       // Ahi,Alo,Bhi,Blo
#define NST  4
#define GEMM_SMEM (NST*STAGEF*4)   // 98304 bytes

// scratch
__device__ float g_whi[4][DD*DD];   // split (transposed) weights hi
__device__ float g_wlo[4][DD*DD];   // split weights lo
__device__ float g_xhi[NN*DD];      // split activation hi (reused per GEMM)
__device__ float g_xlo[NN*DD];      // split activation lo
__device__ float g_q[NN*DD];        // [B,S,H,DK] == [8192][1024]
__device__ float g_k[NN*DD];
__device__ float g_v[NN*DD];
__device__ float g_c[NN*DD];

__device__ __forceinline__ uint32_t smem_u32(const void* p) {
    uint32_t a;
    asm("{ .reg .u64 t; cvta.to.shared.u64 t, %1; cvt.u32.u64 %0, t; }" : "=r"(a) : "l"(p));
    return a;
}
__device__ __forceinline__ float tf32r(float x) {
    uint32_t u;
    asm("cvt.rna.tf32.f32 %0, %1;" : "=r"(u) : "f"(x));
    return __uint_as_float(u);
}
__device__ __forceinline__ void cpa16(uint32_t s, const void* g) {
    asm volatile("cp.async.cg.shared.global [%0], [%1], 16;" :: "r"(s), "l"(g));
}
__device__ __forceinline__ void cpa_commit() {
    asm volatile("cp.async.commit_group;" ::: "memory");
}
__device__ __forceinline__ void cpa_wait2() {
    asm volatile("cp.async.wait_group 2;" ::: "memory");
}
__device__ __forceinline__ void mma8(float* d, const float* a, const float* b) {
    asm volatile("mma.sync.aligned.m16n8k8.row.col.f32.tf32.tf32.f32 "
        "{%0,%1,%2,%3}, {%4,%5,%6,%7}, {%8,%9}, {%0,%1,%2,%3};"
        : "+f"(d[0]), "+f"(d[1]), "+f"(d[2]), "+f"(d[3])
        : "r"(__float_as_uint(a[0])), "r"(__float_as_uint(a[1])),
          "r"(__float_as_uint(a[2])), "r"(__float_as_uint(a[3])),
          "r"(__float_as_uint(b[0])), "r"(__float_as_uint(b[1])));
}

// ---------------------------------------------------------------------------
// split: X -> hi/lo tf32 planes (vectorized)
// ---------------------------------------------------------------------------
__global__ void split_kernel(const float4* __restrict__ X, float4* __restrict__ hi,
                             float4* __restrict__ lo, int n4)
{
    int i = blockIdx.x * blockDim.x + threadIdx.x;
    if (i < n4) {
        float4 x = X[i];
        float4 h, l;
        h.x = tf32r(x.x); l.x = tf32r(x.x - h.x);
        h.y = tf32r(x.y); l.y = tf32r(x.y - h.y);
        h.z = tf32r(x.z); l.z = tf32r(x.z - h.z);
        h.w = tf32r(x.w); l.w = tf32r(x.w - h.w);
        hi[i] = h; lo[i] = l;
    }
}

// ---------------------------------------------------------------------------
// Weight transpose + split: Whi/Wlo[h*64+dk][d] = split(W[h][d][dk])
// ---------------------------------------------------------------------------
__global__ void transpose_split_w(const float* __restrict__ W,
                                  float* __restrict__ Whi, float* __restrict__ Wlo)
{
    __shared__ float t[32][33];
    const int h  = blockIdx.z;
    const int d0 = blockIdx.y << 5;
    const int k0 = blockIdx.x << 5;
    const int c  = threadIdx.x & 31;
    const int r4 = threadIdx.x >> 5;
    const float* Wh = W + ((size_t)h << 16);
    #pragma unroll
    for (int i = 0; i < 4; i++)
        t[r4 + 8*i][c] = Wh[(size_t)(d0 + r4 + 8*i) * DKK + k0 + c];
    __syncthreads();
    const size_t ob = (size_t)(h * DKK + k0) * DD + d0;
    #pragma unroll
    for (int i = 0; i < 4; i++) {
        float v  = t[c][r4 + 8*i];
        float hv = tf32r(v);
        Whi[ob + (size_t)(r4 + 8*i) * DD + c] = hv;
        Wlo[ob + (size_t)(r4 + 8*i) * DD + c] = tf32r(v - hv);
    }
}

// ---------------------------------------------------------------------------
// tf32x3 warp-MMA GEMM on pre-split planes:
// C[m][n] = sum_k (Ahi+Alo)[m][k]*(Bhi+Blo)[n][k] (+bias[n]), 3-product split.
// 256 threads, BM=128 BN=128 BK=8, 4-stage cp.async, 2 CTAs/SM.
// ---------------------------------------------------------------------------
__global__ __launch_bounds__(256, 2)
void gemm_tf32(const float* __restrict__ Ahi, const float* __restrict__ Alo,
               const float* __restrict__ Bhi, const float* __restrict__ Blo,
               const float* __restrict__ bias, float* __restrict__ C)
{
    extern __shared__ float sm[];
    const uint32_t smb = smem_u32(sm);
    const int tid  = threadIdx.x;
    const int m0   = blockIdx.y * BM;
    const int n0   = blockIdx.x * BN;
    const int w    = tid >> 5, lane = tid & 31;
    const int grp  = lane >> 2, tig = lane & 3;
    const int m_off = (w >> 2) * 64;
    const int n_off = (w & 3) * 32;

    // loader: 1 float4 per plane per thread (128 rows x 2 float4/row = 256)
    const int lrow = tid >> 1, lc4 = (tid & 1) * 4;

    float acc[4][4][4];
    #pragma unroll
    for (int t = 0; t < 4; t++)
        #pragma unroll
        for (int u = 0; u < 4; u++)
            #pragma unroll
            for (int q = 0; q < 4; q++) acc[t][u][q] = 0.f;

    #define ISSUE(k0idx)                                                          \
    {                                                                             \
        const int kk0 = (k0idx) * BK;                                             \
        const uint32_t st = smb + (uint32_t)((k0idx) & (NST-1)) * (STAGEF * 4u);  \
        const uint32_t so = (uint32_t)(lrow * RS + lc4) * 4u;                     \
        cpa16(st + so,                     Ahi + (size_t)(m0 + lrow)*DD + kk0 + lc4); \
        cpa16(st + PLANEF*4u   + so,       Alo + (size_t)(m0 + lrow)*DD + kk0 + lc4); \
        cpa16(st + 2*PLANEF*4u + so,       Bhi + (size_t)(n0 + lrow)*DD + kk0 + lc4); \
        cpa16(st + 3*PLANEF*4u + so,       Blo + (size_t)(n0 + lrow)*DD + kk0 + lc4); \
    }

    ISSUE(0); cpa_commit();
    ISSUE(1); cpa_commit();
    ISSUE(2); cpa_commit();

    for (int c = 0; c < NIT; ++c) {
        cpa_wait2();
        __syncthreads();

        const float* AHI = sm + (c & (NST - 1)) * STAGEF;
        const float* ALO = AHI + PLANEF;
        const float* BHI = AHI + 2 * PLANEF;
        const float* BLO = AHI + 3 * PLANEF;

        float ah[4][4], al[4][4];
        #pragma unroll
        for (int t = 0; t < 4; t++) {
            const int r = m_off + t * 16 + grp;
            ah[t][0] = AHI[r*RS + tig];         al[t][0] = ALO[r*RS + tig];
            ah[t][1] = AHI[(r+8)*RS + tig];     al[t][1] = ALO[(r+8)*RS + tig];
            ah[t][2] = AHI[r*RS + tig + 4];     al[t][2] = ALO[r*RS + tig + 4];
            ah[t][3] = AHI[(r+8)*RS + tig + 4]; al[t][3] = ALO[(r+8)*RS + tig + 4];
        }
        #pragma unroll
        for (int u = 0; u < 4; u++) {
            const int n = n_off + u * 8 + grp;
            float bh[2], bl[2];
            bh[0] = BHI[n*RS + tig];     bl[0] = BLO[n*RS + tig];
            bh[1] = BHI[n*RS + tig + 4]; bl[1] = BLO[n*RS + tig + 4];
            #pragma unroll
            for (int t = 0; t < 4; t++) {
                mma8(acc[t][u], ah[t], bh);
                mma8(acc[t][u], ah[t], bl);
                mma8(acc[t][u], al[t], bh);
            }
        }

        if (c + 3 < NIT) ISSUE(c + 3);
        cpa_commit();
    }
    #undef ISSUE

    const bool hasb = (bias != nullptr);
    #pragma unroll
    for (int u = 0; u < 4; u++) {
        const int ncol = n0 + n_off + u * 8 + tig * 2;
        float2 bv = make_float2(0.f, 0.f);
        if (hasb) bv = *reinterpret_cast<const float2*>(bias + ncol);
        #pragma unroll
        for (int t = 0; t < 4; t++) {
            const int r = m0 + m_off + t * 16 + grp;
            *reinterpret_cast<float2*>(C + (size_t)r * DD + ncol) =
                make_float2(acc[t][u][0] + bv.x, acc[t][u][1] + bv.y);
            *reinterpret_cast<float2*>(C + (size_t)(r + 8) * DD + ncol) =
                make_float2(acc[t][u][2] + bv.x, acc[t][u][3] + bv.y);
        }
    }
}

// ---------------------------------------------------------------------------
// Causal flash attention, fp32 FFMA. q/k/v layout [B,S,H,DK] (row stride DD).
// ---------------------------------------------------------------------------
__global__ __launch_bounds__(256)
void attn_kernel(const float* __restrict__ gq, const float* __restrict__ gk,
                 const float* __restrict__ gv, float* __restrict__ gc)
{
    extern __shared__ float smf[];
    float* Qs = smf;
    float* Ks = smf + 64*AST;
    float* Vs = smf + 2*64*AST;
    float* Ps = smf + 3*64*AST;

    const int tid = threadIdx.x;
    const int ty  = tid >> 4, tx = tid & 15;
    const int h   = blockIdx.y, b = blockIdx.z;
    const int st  = gridDim.x - 1 - blockIdx.x;
    const int s0  = st * 64;
    const int r0  = ty * 4, c0 = tx * 4;

    const float* qb = gq + ((size_t)b * SS + s0) * DD + h * DKK;
    const float* kb = gk + (size_t)b * SS * DD + h * DKK;
    const float* vb = gv + (size_t)b * SS * DD + h * DKK;

    #pragma unroll
    for (int u = 0; u < 4; u++) {
        int f = tid + u * 256;
        int row = f >> 4, c4 = f & 15;
        *reinterpret_cast<float4*>(Qs + row*AST + c4*4) =
            *reinterpret_cast<const float4*>(qb + (size_t)row * DD + c4*4);
    }

    float m[4], l[4], o[4][4];
    #pragma unroll
    for (int i = 0; i < 4; i++) {
        m[i] = -1e30f; l[i] = 0.f;
        #pragma unroll
        for (int j = 0; j < 4; j++) o[i][j] = 0.f;
    }

    const int ntiles = st + 1;
    for (int tt = 0; tt < ntiles; ++tt) {
        const int t0 = tt * 64;
        __syncthreads();
        #pragma unroll
        for (int u = 0; u < 4; u++) {
            int f = tid + u * 256;
            int row = f >> 4, c4 = f & 15;
            float4 kv = *reinterpret_cast<const float4*>(kb + (size_t)(t0+row) * DD + c4*4);
            Ks[(c4*4+0)*AST + row] = kv.x;
            Ks[(c4*4+1)*AST + row] = kv.y;
            Ks[(c4*4+2)*AST + row] = kv.z;
            Ks[(c4*4+3)*AST + row] = kv.w;
            *reinterpret_cast<float4*>(Vs + row*AST + c4*4) =
                *reinterpret_cast<const float4*>(vb + (size_t)(t0+row) * DD + c4*4);
        }
        __syncthreads();

        float sv[4][4];
        #pragma unroll
        for (int i = 0; i < 4; i++)
            #pragma unroll
            for (int j = 0; j < 4; j++) sv[i][j] = 0.f;

        #pragma unroll 16
        for (int kk = 0; kk < 64; kk++) {
            float a[4];
            #pragma unroll
            for (int i = 0; i < 4; i++) a[i] = Qs[(r0+i)*AST + kk];
            float4 b4 = *reinterpret_cast<const float4*>(Ks + kk*AST + c0);
            float bv[4] = {b4.x, b4.y, b4.z, b4.w};
            #pragma unroll
            for (int i = 0; i < 4; i++)
                #pragma unroll
                for (int j = 0; j < 4; j++)
                    sv[i][j] = fmaf(a[i], bv[j], sv[i][j]);
        }

        #pragma unroll
        for (int i = 0; i < 4; i++)
            #pragma unroll
            for (int j = 0; j < 4; j++) sv[i][j] *= 8.0f;
        if (t0 == s0) {
            #pragma unroll
            for (int i = 0; i < 4; i++)
                #pragma unroll
                for (int j = 0; j < 4; j++)
                    if (c0 + j > r0 + i) sv[i][j] = -1e30f;
        }

        float mt[4];
        #pragma unroll
        for (int i = 0; i < 4; i++)
            mt[i] = fmaxf(fmaxf(sv[i][0], sv[i][1]), fmaxf(sv[i][2], sv[i][3]));
        #pragma unroll
        for (int off = 8; off; off >>= 1)
            #pragma unroll
            for (int i = 0; i < 4; i++)
                mt[i] = fmaxf(mt[i], __shfl_xor_sync(0xffffffffu, mt[i], off));

        float mn[4], alpha[4];
        #pragma unroll
        for (int i = 0; i < 4; i++) {
            mn[i] = fmaxf(m[i], mt[i]);
            alpha[i] = __expf(m[i] - mn[i]);
            m[i] = mn[i];
        }

        float p[4][4], ls[4];
        #pragma unroll
        for (int i = 0; i < 4; i++) {
            ls[i] = 0.f;
            #pragma unroll
            for (int j = 0; j < 4; j++) {
                p[i][j] = __expf(sv[i][j] - mn[i]);
                ls[i] += p[i][j];
            }
        }
        #pragma unroll
        for (int off = 8; off; off >>= 1)
            #pragma unroll
            for (int i = 0; i < 4; i++)
                ls[i] += __shfl_xor_sync(0xffffffffu, ls[i], off);

        #pragma unroll
        for (int i = 0; i < 4; i++) {
            l[i] = l[i] * alpha[i] + ls[i];
            #pragma unroll
            for (int j = 0; j < 4; j++) o[i][j] *= alpha[i];
        }

        #pragma unroll
        for (int i = 0; i < 4; i++)
            *reinterpret_cast<float4*>(Ps + (r0+i)*AST + c0) =
                make_float4(p[i][0], p[i][1], p[i][2], p[i][3]);
        __syncthreads();

        #pragma unroll 16
        for (int kk = 0; kk < 64; kk++) {
            float a[4];
            #pragma unroll
            for (int i = 0; i < 4; i++) a[i] = Ps[(r0+i)*AST + kk];
            float4 b4 = *reinterpret_cast<const float4*>(Vs + kk*AST + c0);
            float bv[4] = {b4.x, b4.y, b4.z, b4.w};
            #pragma unroll
            for (int i = 0; i < 4; i++)
                #pragma unroll
                for (int j = 0; j < 4; j++)
                    o[i][j] = fmaf(a[i], bv[j], o[i][j]);
        }
    }

    float* outp = gc + ((size_t)b * SS + s0) * DD + h * DKK;
    #pragma unroll
    for (int i = 0; i < 4; i++) {
        float inv = 1.0f / l[i];
        float4 ov = make_float4(o[i][0]*inv, o[i][1]*inv, o[i][2]*inv, o[i][3]*inv);
        *reinterpret_cast<float4*>(outp + (size_t)(r0+i) * DD + c0) = ov;
    }
}

// ---------------------------------------------------------------------------
extern "C" void kernel_launch(void* const* d_in, const int* in_sizes, int n_in,
                              void* d_out, int out_size)
{
    const float* Q  = (const float*)d_in[0];
    const float* K  = (const float*)d_in[1];
    const float* V  = (const float*)d_in[2];
    // d_in[3] = causal mask (unused)
    const float* Wq = (const float*)d_in[4];
    const float* Wk = (const float*)d_in[5];
    const float* Wv = (const float*)d_in[6];
    const float* Wo = (const float*)d_in[7];
    const float* bo = (const float*)d_in[8];
    float* out = (float*)d_out;

    float *whi, *wlo, *xhi, *xlo, *gq, *gk, *gv, *gc;
    cudaGetSymbolAddress((void**)&whi, g_whi);
    cudaGetSymbolAddress((void**)&wlo, g_wlo);
    cudaGetSymbolAddress((void**)&xhi, g_xhi);
    cudaGetSymbolAddress((void**)&xlo, g_xlo);
    cudaGetSymbolAddress((void**)&gq,  g_q);
    cudaGetSymbolAddress((void**)&gk,  g_k);
    cudaGetSymbolAddress((void**)&gv,  g_v);
    cudaGetSymbolAddress((void**)&gc,  g_c);
    const size_t WSZ = (size_t)DD * DD;

    cudaFuncSetAttribute(gemm_tf32, cudaFuncAttributeMaxDynamicSharedMemorySize, GEMM_SMEM);
    int asmem = 4 * 64 * AST * (int)sizeof(float);
    cudaFuncSetAttribute(attn_kernel, cudaFuncAttributeMaxDynamicSharedMemorySize, asmem);

    const dim3 tg(DKK / 32, DD / 32, HH);     // (2, 32, 16)
    const dim3 gg(DD / BN, NN / BM);          // (8, 64)
    const int  nx4 = NN * DD / 4;             // activation float4 count
    const int  nw4 = DD * DD / 4;

    // weights
    transpose_split_w<<<tg, 256>>>(Wq, whi + 0*WSZ, wlo + 0*WSZ);
    transpose_split_w<<<tg, 256>>>(Wk, whi + 1*WSZ, wlo + 1*WSZ);
    transpose_split_w<<<tg, 256>>>(Wv, whi + 2*WSZ, wlo + 2*WSZ);
    split_kernel<<<(nw4 + 255)/256, 256>>>((const float4*)Wo,
                                           (float4*)(whi + 3*WSZ), (float4*)(wlo + 3*WSZ), nw4);

    // projections
    split_kernel<<<(nx4 + 255)/256, 256>>>((const float4*)Q, (float4*)xhi, (float4*)xlo, nx4);
    gemm_tf32<<<gg, 256, GEMM_SMEM>>>(xhi, xlo, whi + 0*WSZ, wlo + 0*WSZ, nullptr, gq);
    split_kernel<<<(nx4 + 255)/256, 256>>>((const float4*)K, (float4*)xhi, (float4*)xlo, nx4);
    gemm_tf32<<<gg, 256, GEMM_SMEM>>>(xhi, xlo, whi + 1*WSZ, wlo + 1*WSZ, nullptr, gk);
    split_kernel<<<(nx4 + 255)/256, 256>>>((const float4*)V, (float4*)xhi, (float4*)xlo, nx4);
    gemm_tf32<<<gg, 256, GEMM_SMEM>>>(xhi, xlo, whi + 2*WSZ, wlo + 2*WSZ, nullptr, gv);

    // attention
    attn_kernel<<<dim3(SS/64, HH, BB), 256, asmem>>>(gq, gk, gv, gc);

    // output projection
    split_kernel<<<(nx4 + 255)/256, 256>>>((const float4*)gc, (float4*)xhi, (float4*)xlo, nx4);
    gemm_tf32<<<gg, 256, GEMM_SMEM>>>(xhi, xlo, whi + 3*WSZ, wlo + 3*WSZ, bo, out);
}

// round 6
// speedup vs baseline: 1.3191x; 1.3191x over previous
#include <cuda_runtime.h>
#include <cstdint>

#define BB  4
#define SS  2048
#define DD  1024
#define HH  16
#define DKK 64
#define NN  (BB*SS)

// ---- warp-MMA GEMM tiling (round-3 config: known 314us) ----
#define BM   128
#define BN   128
#define BK   16
#define NIT  (DD/BK)            // 64
#define RS   20                 // smem row stride (floats), conflict-free
#define PLANE (BM*RS)           // 2560 floats per plane
#define STAGEF (4*PLANE)        // Ahi,Alo,Bhi,Blo
#define GEMM_SMEM (2*STAGEF*4)  // 81920 bytes

// ---- attention tiling ----
#define TQ   128
#define TKV  64
#define KST  68
#define ATTN_SMEM ((4*64*KST + TQ*KST)*4)   // 104448 bytes

// scratch
__device__ float g_wt[3][DD*DD];
__device__ float g_q[NN*DD];    // [B,S,H,DK] == [8192][1024]
__device__ float g_k[NN*DD];
__device__ float g_v[NN*DD];
__device__ float g_c[NN*DD];

__device__ __forceinline__ float tf32r(float x) {
    uint32_t u;
    asm("cvt.rna.tf32.f32 %0, %1;" : "=r"(u) : "f"(x));
    return __uint_as_float(u);
}
__device__ __forceinline__ void mma8(float* d, const float* a, const float* b) {
    asm volatile("mma.sync.aligned.m16n8k8.row.col.f32.tf32.tf32.f32 "
        "{%0,%1,%2,%3}, {%4,%5,%6,%7}, {%8,%9}, {%0,%1,%2,%3};"
        : "+f"(d[0]), "+f"(d[1]), "+f"(d[2]), "+f"(d[3])
        : "r"(__float_as_uint(a[0])), "r"(__float_as_uint(a[1])),
          "r"(__float_as_uint(a[2])), "r"(__float_as_uint(a[3])),
          "r"(__float_as_uint(b[0])), "r"(__float_as_uint(b[1])));
}

// ---------------------------------------------------------------------------
// Weight transpose: Wt[h*64+dk][d] = W[h][d][dk]
// ---------------------------------------------------------------------------
__global__ void transpose_w(const float* __restrict__ W, float* __restrict__ Wt) {
    __shared__ float t[32][33];
    const int h  = blockIdx.z;
    const int d0 = blockIdx.y << 5;
    const int k0 = blockIdx.x << 5;
    const int c  = threadIdx.x & 31;
    const int r4 = threadIdx.x >> 5;
    const float* Wh = W + ((size_t)h << 16);
    #pragma unroll
    for (int i = 0; i < 4; i++)
        t[r4 + 8*i][c] = Wh[(size_t)(d0 + r4 + 8*i) * DKK + k0 + c];
    __syncthreads();
    float* o = Wt + (size_t)(h * DKK + k0) * DD + d0;
    #pragma unroll
    for (int i = 0; i < 4; i++)
        o[(size_t)(r4 + 8*i) * DD + c] = t[c][r4 + 8*i];
}

// ---------------------------------------------------------------------------
// tf32x3 warp-MMA GEMM (round-3 version, verbatim): C = A B^T (+bias)
// ---------------------------------------------------------------------------
__global__ __launch_bounds__(256, 1)
void gemm_tf32(const float* __restrict__ A, const float* __restrict__ B,
               const float* __restrict__ bias, float* __restrict__ C)
{
    extern __shared__ float sm[];
    const int tid  = threadIdx.x;
    const int m0   = blockIdx.y * BM;
    const int n0   = blockIdx.x * BN;
    const int w    = tid >> 5, lane = tid & 31;
    const int grp  = lane >> 2, tig = lane & 3;
    const int m_off = (w >> 2) * 64;
    const int n_off = (w & 3) * 32;

    const int lrow0 = tid >> 2, lc4 = (tid & 3) * 4;
    const int lrow1 = lrow0 + 64;

    float acc[4][4][4];
    #pragma unroll
    for (int t = 0; t < 4; t++)
        #pragma unroll
        for (int u = 0; u < 4; u++)
            #pragma unroll
            for (int q = 0; q < 4; q++) acc[t][u][q] = 0.f;

    float4 ra0, ra1, rb0, rb1;
    ra0 = *reinterpret_cast<const float4*>(A + (size_t)(m0 + lrow0) * DD + lc4);
    ra1 = *reinterpret_cast<const float4*>(A + (size_t)(m0 + lrow1) * DD + lc4);
    rb0 = *reinterpret_cast<const float4*>(B + (size_t)(n0 + lrow0) * DD + lc4);
    rb1 = *reinterpret_cast<const float4*>(B + (size_t)(n0 + lrow1) * DD + lc4);

    #define SPLIT_STORE(stage)                                                    \
    {                                                                             \
        float* AHI = sm + (stage) * STAGEF;                                       \
        float* ALO = AHI + PLANE;                                                 \
        float* BHI = AHI + 2 * PLANE;                                             \
        float* BLO = AHI + 3 * PLANE;                                             \
        float4 h, l;                                                              \
        h.x=tf32r(ra0.x); l.x=tf32r(ra0.x-h.x); h.y=tf32r(ra0.y); l.y=tf32r(ra0.y-h.y); \
        h.z=tf32r(ra0.z); l.z=tf32r(ra0.z-h.z); h.w=tf32r(ra0.w); l.w=tf32r(ra0.w-h.w); \
        *reinterpret_cast<float4*>(AHI + lrow0*RS + lc4) = h;                     \
        *reinterpret_cast<float4*>(ALO + lrow0*RS + lc4) = l;                     \
        h.x=tf32r(ra1.x); l.x=tf32r(ra1.x-h.x); h.y=tf32r(ra1.y); l.y=tf32r(ra1.y-h.y); \
        h.z=tf32r(ra1.z); l.z=tf32r(ra1.z-h.z); h.w=tf32r(ra1.w); l.w=tf32r(ra1.w-h.w); \
        *reinterpret_cast<float4*>(AHI + lrow1*RS + lc4) = h;                     \
        *reinterpret_cast<float4*>(ALO + lrow1*RS + lc4) = l;                     \
        h.x=tf32r(rb0.x); l.x=tf32r(rb0.x-h.x); h.y=tf32r(rb0.y); l.y=tf32r(rb0.y-h.y); \
        h.z=tf32r(rb0.z); l.z=tf32r(rb0.z-h.z); h.w=tf32r(rb0.w); l.w=tf32r(rb0.w-h.w); \
        *reinterpret_cast<float4*>(BHI + lrow0*RS + lc4) = h;                     \
        *reinterpret_cast<float4*>(BLO + lrow0*RS + lc4) = l;                     \
        h.x=tf32r(rb1.x); l.x=tf32r(rb1.x-h.x); h.y=tf32r(rb1.y); l.y=tf32r(rb1.y-h.y); \
        h.z=tf32r(rb1.z); l.z=tf32r(rb1.z-h.z); h.w=tf32r(rb1.w); l.w=tf32r(rb1.w-h.w); \
        *reinterpret_cast<float4*>(BHI + lrow1*RS + lc4) = h;                     \
        *reinterpret_cast<float4*>(BLO + lrow1*RS + lc4) = l;                     \
    }

    SPLIT_STORE(0);
    __syncthreads();

    for (int c = 0; c < NIT; ++c) {
        if (c + 1 < NIT) {
            const int k0 = (c + 1) * BK;
            ra0 = *reinterpret_cast<const float4*>(A + (size_t)(m0 + lrow0) * DD + k0 + lc4);
            ra1 = *reinterpret_cast<const float4*>(A + (size_t)(m0 + lrow1) * DD + k0 + lc4);
            rb0 = *reinterpret_cast<const float4*>(B + (size_t)(n0 + lrow0) * DD + k0 + lc4);
            rb1 = *reinterpret_cast<const float4*>(B + (size_t)(n0 + lrow1) * DD + k0 + lc4);
        }

        const float* AHI = sm + (c & 1) * STAGEF;
        const float* ALO = AHI + PLANE;
        const float* BHI = AHI + 2 * PLANE;
        const float* BLO = AHI + 3 * PLANE;

        #pragma unroll
        for (int s = 0; s < 2; ++s) {
            const int kk = s * 8;
            float ah[4][4], al[4][4], bh[4][2], bl[4][2];
            #pragma unroll
            for (int t = 0; t < 4; t++) {
                const int r = m_off + t * 16 + grp;
                const int cidx = kk + tig;
                ah[t][0] = AHI[r*RS + cidx];       al[t][0] = ALO[r*RS + cidx];
                ah[t][1] = AHI[(r+8)*RS + cidx];   al[t][1] = ALO[(r+8)*RS + cidx];
                ah[t][2] = AHI[r*RS + cidx + 4];   al[t][2] = ALO[r*RS + cidx + 4];
                ah[t][3] = AHI[(r+8)*RS + cidx+4]; al[t][3] = ALO[(r+8)*RS + cidx+4];
            }
            #pragma unroll
            for (int u = 0; u < 4; u++) {
                const int n = n_off + u * 8 + grp;
                const int cidx = kk + tig;
                bh[u][0] = BHI[n*RS + cidx];     bl[u][0] = BLO[n*RS + cidx];
                bh[u][1] = BHI[n*RS + cidx + 4]; bl[u][1] = BLO[n*RS + cidx + 4];
            }
            #pragma unroll
            for (int t = 0; t < 4; t++)
                #pragma unroll
                for (int u = 0; u < 4; u++) {
                    mma8(acc[t][u], ah[t], bh[u]);
                    mma8(acc[t][u], ah[t], bl[u]);
                    mma8(acc[t][u], al[t], bh[u]);
                }
        }

        if (c + 1 < NIT) SPLIT_STORE((c + 1) & 1);
        __syncthreads();
    }

    const bool hasb = (bias != nullptr);
    #pragma unroll
    for (int u = 0; u < 4; u++) {
        const int ncol = n0 + n_off + u * 8 + tig * 2;
        float2 bv = make_float2(0.f, 0.f);
        if (hasb) bv = *reinterpret_cast<const float2*>(bias + ncol);
        #pragma unroll
        for (int t = 0; t < 4; t++) {
            const int r = m0 + m_off + t * 16 + grp;
            *reinterpret_cast<float2*>(C + (size_t)r * DD + ncol) =
                make_float2(acc[t][u][0] + bv.x, acc[t][u][1] + bv.y);
            *reinterpret_cast<float2*>(C + (size_t)(r + 8) * DD + ncol) =
                make_float2(acc[t][u][2] + bv.x, acc[t][u][3] + bv.y);
        }
    }
    #undef SPLIT_STORE
}

// ---------------------------------------------------------------------------
// Causal flash attention with mma.sync tf32.
// QK: tf32x3 (q,k hi/lo).  PV: P rounded to tf32, V split hi/lo (2 products).
// CTA: 128 q-rows, 8 warps (warp = m16 x full 64 kv / 64 dk). scale = 8.
// q/k/v layout [B,S,H,DK] (row stride DD); output concat [B,S,D].
// ---------------------------------------------------------------------------
__global__ __launch_bounds__(256, 1)
void attn_mma(const float* __restrict__ gq, const float* __restrict__ gk,
              const float* __restrict__ gv, float* __restrict__ gc)
{
    extern __shared__ float smf[];
    float* Khi  = smf;                 // [64][KST] K natural [kv][dk]
    float* Klo  = smf + 64*KST;
    float* Vthi = smf + 2*64*KST;      // [64][KST] V transposed [dk][kv]
    float* Vtlo = smf + 3*64*KST;
    float* Ps   = smf + 4*64*KST;      // [128][KST] P (tf32-rounded)

    const int tid  = threadIdx.x;
    const int w    = tid >> 5, lane = tid & 31;
    const int grp  = lane >> 2, tig = lane & 3;
    const int wrow = w * 16;
    const int h    = blockIdx.y, b = blockIdx.z;
    const int st   = gridDim.x - 1 - blockIdx.x;   // big blocks first
    const int s0   = st * TQ;

    const float* qb = gq + ((size_t)b * SS + s0) * DD + h * DKK;
    const float* kb = gk + (size_t)b * SS * DD + h * DKK;
    const float* vb = gv + (size_t)b * SS * DD + h * DKK;

    // ---- stage Q (split) and extract A-fragments ----
    {
        float* Qhi = Ps;    // 128*KST floats
        float* Qlo = Khi;   // Khi..Klo span = 2*64*KST = 128*KST floats
        #pragma unroll
        for (int u = 0; u < 8; u++) {
            int f = tid + u * 256;
            int row = f >> 4, c4 = f & 15;
            float4 x = *reinterpret_cast<const float4*>(qb + (size_t)row * DD + c4 * 4);
            float4 hv, lv;
            hv.x = tf32r(x.x); lv.x = tf32r(x.x - hv.x);
            hv.y = tf32r(x.y); lv.y = tf32r(x.y - hv.y);
            hv.z = tf32r(x.z); lv.z = tf32r(x.z - hv.z);
            hv.w = tf32r(x.w); lv.w = tf32r(x.w - hv.w);
            *reinterpret_cast<float4*>(Qhi + row * KST + c4 * 4) = hv;
            *reinterpret_cast<float4*>(Qlo + row * KST + c4 * 4) = lv;
        }
    }
    __syncthreads();
    float aqh[8][4], aql[8][4];
    #pragma unroll
    for (int ks = 0; ks < 8; ks++) {
        const int base = (wrow + grp) * KST + ks * 8 + tig;
        aqh[ks][0] = Ps[base];             aqh[ks][1] = Ps[base + 8*KST];
        aqh[ks][2] = Ps[base + 4];         aqh[ks][3] = Ps[base + 8*KST + 4];
        aql[ks][0] = Khi[base];            aql[ks][1] = Khi[base + 8*KST];
        aql[ks][2] = Khi[base + 4];        aql[ks][3] = Khi[base + 8*KST + 4];
    }
    __syncthreads();   // Q staging consumed; smem free for K/V

    // prefetch K/V tile 0 into registers (4 float4 each)
    float4 kreg[4], vreg[4];
    #pragma unroll
    for (int u = 0; u < 4; u++) {
        int f = tid + u * 256;
        int row = f >> 4, c4 = f & 15;
        kreg[u] = *reinterpret_cast<const float4*>(kb + (size_t)row * DD + c4 * 4);
        vreg[u] = *reinterpret_cast<const float4*>(vb + (size_t)row * DD + c4 * 4);
    }

    float m0r = -1e30f, m1r = -1e30f, l0 = 0.f, l1 = 0.f;
    float of[8][4];
    #pragma unroll
    for (int nt = 0; nt < 8; nt++)
        #pragma unroll
        for (int q = 0; q < 4; q++) of[nt][q] = 0.f;

    const int ntiles = s0 / TKV + 2;
    for (int tt = 0; tt < ntiles; ++tt) {
        // store prefetched K/V into smem (split; V transposed)
        #pragma unroll
        for (int u = 0; u < 4; u++) {
            int f = tid + u * 256;
            int row = f >> 4, c4 = f & 15;
            float4 x = kreg[u];
            float4 hv, lv;
            hv.x = tf32r(x.x); lv.x = tf32r(x.x - hv.x);
            hv.y = tf32r(x.y); lv.y = tf32r(x.y - hv.y);
            hv.z = tf32r(x.z); lv.z = tf32r(x.z - hv.z);
            hv.w = tf32r(x.w); lv.w = tf32r(x.w - hv.w);
            *reinterpret_cast<float4*>(Khi + row * KST + c4 * 4) = hv;
            *reinterpret_cast<float4*>(Klo + row * KST + c4 * 4) = lv;
            float4 y = vreg[u];
            float vh, vl;
            vh = tf32r(y.x); vl = tf32r(y.x - vh);
            Vthi[(c4*4+0)*KST + row] = vh; Vtlo[(c4*4+0)*KST + row] = vl;
            vh = tf32r(y.y); vl = tf32r(y.y - vh);
            Vthi[(c4*4+1)*KST + row] = vh; Vtlo[(c4*4+1)*KST + row] = vl;
            vh = tf32r(y.z); vl = tf32r(y.z - vh);
            Vthi[(c4*4+2)*KST + row] = vh; Vtlo[(c4*4+2)*KST + row] = vl;
            vh = tf32r(y.w); vl = tf32r(y.w - vh);
            Vthi[(c4*4+3)*KST + row] = vh; Vtlo[(c4*4+3)*KST + row] = vl;
        }
        __syncthreads();

        // prefetch next tile
        if (tt + 1 < ntiles) {
            const int t0n = (tt + 1) * TKV;
            #pragma unroll
            for (int u = 0; u < 4; u++) {
                int f = tid + u * 256;
                int row = f >> 4, c4 = f & 15;
                kreg[u] = *reinterpret_cast<const float4*>(kb + (size_t)(t0n + row) * DD + c4 * 4);
                vreg[u] = *reinterpret_cast<const float4*>(vb + (size_t)(t0n + row) * DD + c4 * 4);
            }
        }

        // ---- S = Q K^T (tf32 x3) ----
        float sf[8][4];
        #pragma unroll
        for (int nt = 0; nt < 8; nt++)
            #pragma unroll
            for (int q = 0; q < 4; q++) sf[nt][q] = 0.f;

        #pragma unroll
        for (int ks = 0; ks < 8; ks++) {
            #pragma unroll
            for (int nt = 0; nt < 8; nt++) {
                const int bbx = (nt*8 + grp) * KST + ks*8 + tig;
                float bh[2] = { Khi[bbx], Khi[bbx + 4] };
                float bl[2] = { Klo[bbx], Klo[bbx + 4] };
                mma8(sf[nt], aqh[ks], bh);
                mma8(sf[nt], aql[ks], bh);
                mma8(sf[nt], aqh[ks], bl);
            }
        }

        // scale + causal mask
        const int t0 = tt * TKV;
        #pragma unroll
        for (int nt = 0; nt < 8; nt++)
            #pragma unroll
            for (int q = 0; q < 4; q++) sf[nt][q] *= 8.0f;
        if (t0 + TKV > s0) {
            const int r0g = s0 + wrow + grp, r1g = r0g + 8;
            #pragma unroll
            for (int nt = 0; nt < 8; nt++) {
                const int c0g = t0 + nt*8 + 2*tig;
                if (c0g     > r0g) sf[nt][0] = -1e30f;
                if (c0g + 1 > r0g) sf[nt][1] = -1e30f;
                if (c0g     > r1g) sf[nt][2] = -1e30f;
                if (c0g + 1 > r1g) sf[nt][3] = -1e30f;
            }
        }

        // row max (rows grp / grp+8) across 16 cols + quad lanes
        float mt0 = -1e30f, mt1 = -1e30f;
        #pragma unroll
        for (int nt = 0; nt < 8; nt++) {
            mt0 = fmaxf(mt0, fmaxf(sf[nt][0], sf[nt][1]));
            mt1 = fmaxf(mt1, fmaxf(sf[nt][2], sf[nt][3]));
        }
        mt0 = fmaxf(mt0, __shfl_xor_sync(0xffffffffu, mt0, 1));
        mt0 = fmaxf(mt0, __shfl_xor_sync(0xffffffffu, mt0, 2));
        mt1 = fmaxf(mt1, __shfl_xor_sync(0xffffffffu, mt1, 1));
        mt1 = fmaxf(mt1, __shfl_xor_sync(0xffffffffu, mt1, 2));

        const float mn0 = fmaxf(m0r, mt0), mn1 = fmaxf(m1r, mt1);
        const float a0 = __expf(m0r - mn0), a1 = __expf(m1r - mn1);
        m0r = mn0; m1r = mn1;

        float s0sum = 0.f, s1sum = 0.f;
        #pragma unroll
        for (int nt = 0; nt < 8; nt++) {
            float p0 = __expf(sf[nt][0] - mn0);
            float p1 = __expf(sf[nt][1] - mn0);
            float p2 = __expf(sf[nt][2] - mn1);
            float p3 = __expf(sf[nt][3] - mn1);
            s0sum += p0 + p1; s1sum += p2 + p3;
            *reinterpret_cast<float2*>(Ps + (wrow + grp) * KST + nt*8 + 2*tig) =
                make_float2(tf32r(p0), tf32r(p1));
            *reinterpret_cast<float2*>(Ps + (wrow + grp + 8) * KST + nt*8 + 2*tig) =
                make_float2(tf32r(p2), tf32r(p3));
        }
        s0sum += __shfl_xor_sync(0xffffffffu, s0sum, 1);
        s0sum += __shfl_xor_sync(0xffffffffu, s0sum, 2);
        s1sum += __shfl_xor_sync(0xffffffffu, s1sum, 1);
        s1sum += __shfl_xor_sync(0xffffffffu, s1sum, 2);
        l0 = l0 * a0 + s0sum;
        l1 = l1 * a1 + s1sum;
        #pragma unroll
        for (int nt = 0; nt < 8; nt++) {
            of[nt][0] *= a0; of[nt][1] *= a0;
            of[nt][2] *= a1; of[nt][3] *= a1;
        }

        // ---- O += P V  (P tf32, V hi/lo) ----  (Ps rows are warp-private; no sync needed)
        #pragma unroll
        for (int ks = 0; ks < 8; ks++) {
            const int ab = (wrow + grp) * KST + ks*8 + tig;
            float ap[4] = { Ps[ab], Ps[ab + 8*KST], Ps[ab + 4], Ps[ab + 8*KST + 4] };
            #pragma unroll
            for (int nt = 0; nt < 8; nt++) {
                const int bbx = (nt*8 + grp) * KST + ks*8 + tig;
                float bh[2] = { Vthi[bbx], Vthi[bbx + 4] };
                float bl[2] = { Vtlo[bbx], Vtlo[bbx + 4] };
                mma8(of[nt], ap, bh);
                mma8(of[nt], ap, bl);
            }
        }
        __syncthreads();   // guard K/V/Ps reuse next iteration
    }

    // epilogue: normalize, write concat [B,S,D]
    const float inv0 = 1.0f / l0, inv1 = 1.0f / l1;
    float* ob = gc + ((size_t)b * SS + s0 + wrow + grp) * DD + h * DKK;
    #pragma unroll
    for (int nt = 0; nt < 8; nt++) {
        const int col = nt*8 + 2*tig;
        *reinterpret_cast<float2*>(ob + col) =
            make_float2(of[nt][0] * inv0, of[nt][1] * inv0);
        *reinterpret_cast<float2*>(ob + (size_t)8 * DD + col) =
            make_float2(of[nt][2] * inv1, of[nt][3] * inv1);
    }
}

// ---------------------------------------------------------------------------
extern "C" void kernel_launch(void* const* d_in, const int* in_sizes, int n_in,
                              void* d_out, int out_size)
{
    const float* Q  = (const float*)d_in[0];
    const float* K  = (const float*)d_in[1];
    const float* V  = (const float*)d_in[2];
    // d_in[3] = causal mask (unused)
    const float* Wq = (const float*)d_in[4];
    const float* Wk = (const float*)d_in[5];
    const float* Wv = (const float*)d_in[6];
    const float* Wo = (const float*)d_in[7];
    const float* bo = (const float*)d_in[8];
    float* out = (float*)d_out;

    float *gwt, *gq, *gk, *gv, *gc;
    cudaGetSymbolAddress((void**)&gwt, g_wt);
    cudaGetSymbolAddress((void**)&gq,  g_q);
    cudaGetSymbolAddress((void**)&gk,  g_k);
    cudaGetSymbolAddress((void**)&gv,  g_v);
    cudaGetSymbolAddress((void**)&gc,  g_c);
    float* gwt0 = gwt;
    float* gwt1 = gwt + (size_t)DD * DD;
    float* gwt2 = gwt + 2 * (size_t)DD * DD;

    cudaFuncSetAttribute(gemm_tf32, cudaFuncAttributeMaxDynamicSharedMemorySize, GEMM_SMEM);
    cudaFuncSetAttribute(attn_mma, cudaFuncAttributeMaxDynamicSharedMemorySize, ATTN_SMEM);

    const dim3 tg(DKK / 32, DD / 32, HH);     // (2, 32, 16)
    const dim3 gg(DD / BN, NN / BM);          // (8, 64)

    transpose_w<<<tg, 256>>>(Wq, gwt0);
    transpose_w<<<tg, 256>>>(Wk, gwt1);
    transpose_w<<<tg, 256>>>(Wv, gwt2);
    gemm_tf32<<<gg, 256, GEMM_SMEM>>>(Q, gwt0, nullptr, gq);
    gemm_tf32<<<gg, 256, GEMM_SMEM>>>(K, gwt1, nullptr, gk);
    gemm_tf32<<<gg, 256, GEMM_SMEM>>>(V, gwt2, nullptr, gv);

    attn_mma<<<dim3(SS/TQ, HH, BB), 256, ATTN_SMEM>>>(gq, gk, gv, gc);

    gemm_tf32<<<gg, 256, GEMM_SMEM>>>(gc, Wo, bo, out);
}